// round 14
// baseline (speedup 1.0000x reference)
#include <cuda_runtime.h>
#include <cuda_bf16.h>
#include <math.h>
#include <stdint.h>

#define N_NODES 50000
#define N_EDGES 640000
#define IN_DIM  5
#define HID     128
#define NUM_GRAPHS 512

// ---------------- scratch (no allocations allowed) ----------------
__device__ float g_agg5[(size_t)N_NODES * IN_DIM];
__device__ int   g_deg[N_NODES];          // zero-init at load; re-zeroed by final_kernel
__device__ int   g_rowptr[N_NODES + 1];
__device__ int   g_cursor[N_NODES];
__device__ int   g_csr_src[N_EDGES];
__device__ int   g_start[NUM_GRAPHS + 1];
__device__ float g_s[N_NODES];            // h2_j . u
__device__ float g_p[N_NODES];            // h2_j . v
__device__ float g_u[HID], g_v[HID], g_c0;
// A3: per node 512 bf16 = [agg_hi(128) | h_hi(128) | agg_lo(128) | h_lo(128)]
__device__ __align__(16) __nv_bfloat16 g_A3[(size_t)N_NODES * 512];
// Hp: packed h copy for the gather: per node 256 bf16, lane-group layout
//     [l*8 .. l*8+3] = h_hi[4l..4l+3], [l*8+4 .. l*8+7] = h_lo[4l..4l+3]
__device__ __align__(16) __nv_bfloat16 g_Hp[(size_t)N_NODES * 256];
// B3: layer-1 weights [N=128 rows][K3=768] bf16, K-contiguous ([W_hi ; W_hi ; W_lo])
__device__ __align__(16) __nv_bfloat16 g_B3[128 * 768];

// ---------------- hist (4 edges/thread) + B3 precompute ----------------
__global__ void hist_b3_kernel(const int* __restrict__ ei,
                               const float* __restrict__ Wr1,
                               const float* __restrict__ Wt1) {
    int idx = blockIdx.x * blockDim.x + threadIdx.x;
    int e4 = idx * 4;
    if (e4 < N_EDGES) {
        int4 d4 = *(const int4*)(ei + N_EDGES + e4);
        atomicAdd(&g_deg[d4.x], 1);
        atomicAdd(&g_deg[d4.y], 1);
        atomicAdd(&g_deg[d4.z], 1);
        atomicAdd(&g_deg[d4.w], 1);
    }
    if (idx < 128 * 768) {
        int n = idx / 768;
        int k3 = idx % 768;
        int seg = k3 / 256, sk = k3 % 256;
        const float* W = (sk < 128) ? Wr1 : Wt1;
        float w = W[(sk & 127) * 128 + n];
        __nv_bfloat16 h = __float2bfloat16(w);
        __nv_bfloat16 v = (seg == 2) ? __float2bfloat16(w - __bfloat162float(h)) : h;
        g_B3[(size_t)n * 768 + k3] = v;
    }
}

// ---------------- scan + graph-segment starts (merged) ----------------
__global__ void scan_starts_kernel(const int* __restrict__ batch) {
    const int t = threadIdx.x;
    if (t <= NUM_GRAPHS) {
        int lo = 0, hi = N_NODES;
        while (lo < hi) {
            int mid = (lo + hi) >> 1;
            if (batch[mid] < t) lo = mid + 1;
            else hi = mid;
        }
        g_start[t] = lo;
    }
    __shared__ int ssum[1024];
    const int CH = (N_NODES + 1023) / 1024;
    int lo = t * CH, hi = min(lo + CH, N_NODES);
    int s = 0;
    for (int i = lo; i < hi; i++) s += g_deg[i];
    ssum[t] = s;
    __syncthreads();
    for (int off = 1; off < 1024; off <<= 1) {
        int v = (t >= off) ? ssum[t - off] : 0;
        __syncthreads();
        ssum[t] += v;
        __syncthreads();
    }
    int run = (t == 0) ? 0 : ssum[t - 1];
    for (int i = lo; i < hi; i++) {
        int d = g_deg[i];
        g_rowptr[i] = run;
        g_cursor[i] = run;
        run += d;
    }
    if (t == 1023) g_rowptr[N_NODES] = run;
}

// ---------------- fill (4 edges/thread) ----------------
__global__ void fill_kernel(const int* __restrict__ ei) {
    int idx = blockIdx.x * blockDim.x + threadIdx.x;
    int e4 = idx * 4;
    if (e4 >= N_EDGES) return;
    int4 s4 = *(const int4*)(ei + e4);
    int4 d4 = *(const int4*)(ei + N_EDGES + e4);
    int p0 = atomicAdd(&g_cursor[d4.x], 1);
    g_csr_src[p0] = s4.x;
    int p1 = atomicAdd(&g_cursor[d4.y], 1);
    g_csr_src[p1] = s4.y;
    int p2 = atomicAdd(&g_cursor[d4.z], 1);
    g_csr_src[p2] = s4.z;
    int p3 = atomicAdd(&g_cursor[d4.w], 1);
    g_csr_src[p3] = s4.w;
}

// ---------------- hi/lo bf16 pair packer ----------------
__device__ __forceinline__ uint32_t pack2_bf16(float fe, float fo, bool lo_mode) {
    uint32_t h;
    asm("cvt.rn.bf16x2.f32 %0, %1, %2;" : "=r"(h) : "f"(fo), "f"(fe));
    if (lo_mode) {
        float he = __uint_as_float(h << 16);
        float ho = __uint_as_float(h & 0xffff0000u);
        float le = fe - he;
        float lo_ = fo - ho;
        asm("cvt.rn.bf16x2.f32 %0, %1, %2;" : "=r"(h) : "f"(lo_), "f"(le));
    }
    return h;
}

// ---------------- layer 0: 5-dim gather ----------------
__global__ void gather5_kernel(const float* __restrict__ x) {
    int node = blockIdx.x * blockDim.x + threadIdx.x;
    if (node >= N_NODES) return;
    int beg = g_rowptr[node], end = g_rowptr[node + 1];
    float a0 = 0.f, a1 = 0.f, a2 = 0.f, a3 = 0.f, a4 = 0.f;
    for (int e = beg; e < end; e++) {
        const float* xs = x + (size_t)g_csr_src[e] * IN_DIM;
        a0 += xs[0]; a1 += xs[1]; a2 += xs[2]; a3 += xs[3]; a4 += xs[4];
    }
    float* o = g_agg5 + (size_t)node * IN_DIM;
    o[0] = a0; o[1] = a1; o[2] = a2; o[3] = a3; o[4] = a4;
}

// ---------------- layer 0: dense (K=5), writes A3 h_hi/h_lo + packed Hp ----------------
__global__ void layer0_dense_kernel(const float* __restrict__ x,
                                    const float* __restrict__ Wr,
                                    const float* __restrict__ br,
                                    const float* __restrict__ Wt) {
    int n = blockIdx.x * 4 + (threadIdx.x >> 7);
    int o = threadIdx.x & 127;
    if (n >= N_NODES) return;
    float acc = br[o];
#pragma unroll
    for (int i = 0; i < IN_DIM; i++) {
        acc = fmaf(g_agg5[(size_t)n * IN_DIM + i], Wr[i * HID + o], acc);
        acc = fmaf(x[(size_t)n * IN_DIM + i],     Wt[i * HID + o], acc);
    }
    float v = fmaxf(acc, 0.f);
    __nv_bfloat16 hb = __float2bfloat16(v);
    __nv_bfloat16 lb = __float2bfloat16(v - __bfloat162float(hb));
    g_A3[(size_t)n * 512 + 128 + o] = hb;
    g_A3[(size_t)n * 512 + 384 + o] = lb;
    // packed: lane-group g = o/4, slot = o%4 ; hi at +0, lo at +4
    int base = (o >> 2) * 8 + (o & 3);
    g_Hp[(size_t)n * 256 + base]     = hb;
    g_Hp[(size_t)n * 256 + base + 4] = lb;
}

// ---------------- 128-dim gather over packed Hp -> A3 agg_hi/agg_lo ----------------
__device__ __forceinline__ void acc2(float& fe, float& fo, uint32_t w) {
    fe += __uint_as_float(w << 16);
    fo += __uint_as_float(w & 0xffff0000u);
}
// one uint4 = {hi(cols a,a+1), hi(cols a+2,a+3), lo(a,a+1), lo(a+2,a+3)}
#define ACC_V4(v) do { \
        acc2(acc.x, acc.y, (v).x); acc2(acc.z, acc.w, (v).y); \
        acc2(acc.x, acc.y, (v).z); acc2(acc.z, acc.w, (v).w); \
    } while (0)

__global__ void gather128_kernel() {
    int node = (blockIdx.x * blockDim.x + threadIdx.x) >> 5;
    int lane = threadIdx.x & 31;
    if (node >= N_NODES) return;
    int beg = g_rowptr[node], end = g_rowptr[node + 1];
    float4 acc = make_float4(0.f, 0.f, 0.f, 0.f);
    const __nv_bfloat16* Hp = g_Hp;
    const uint32_t loff = (uint32_t)lane * 8;
    int e = beg;
    for (; e + 7 < end; e += 8) {
        uint4 v0 = *(const uint4*)(Hp + (size_t)g_csr_src[e + 0] * 256 + loff);
        uint4 v1 = *(const uint4*)(Hp + (size_t)g_csr_src[e + 1] * 256 + loff);
        uint4 v2 = *(const uint4*)(Hp + (size_t)g_csr_src[e + 2] * 256 + loff);
        uint4 v3 = *(const uint4*)(Hp + (size_t)g_csr_src[e + 3] * 256 + loff);
        uint4 v4 = *(const uint4*)(Hp + (size_t)g_csr_src[e + 4] * 256 + loff);
        uint4 v5 = *(const uint4*)(Hp + (size_t)g_csr_src[e + 5] * 256 + loff);
        uint4 v6 = *(const uint4*)(Hp + (size_t)g_csr_src[e + 6] * 256 + loff);
        uint4 v7 = *(const uint4*)(Hp + (size_t)g_csr_src[e + 7] * 256 + loff);
        ACC_V4(v0); ACC_V4(v1); ACC_V4(v2); ACC_V4(v3);
        ACC_V4(v4); ACC_V4(v5); ACC_V4(v6); ACC_V4(v7);
    }
    for (; e + 3 < end; e += 4) {
        uint4 v0 = *(const uint4*)(Hp + (size_t)g_csr_src[e + 0] * 256 + loff);
        uint4 v1 = *(const uint4*)(Hp + (size_t)g_csr_src[e + 1] * 256 + loff);
        uint4 v2 = *(const uint4*)(Hp + (size_t)g_csr_src[e + 2] * 256 + loff);
        uint4 v3 = *(const uint4*)(Hp + (size_t)g_csr_src[e + 3] * 256 + loff);
        ACC_V4(v0); ACC_V4(v1); ACC_V4(v2); ACC_V4(v3);
    }
    for (; e < end; e++) {
        uint4 v0 = *(const uint4*)(Hp + (size_t)g_csr_src[e] * 256 + loff);
        ACC_V4(v0);
    }
    uint32_t ph0 = pack2_bf16(acc.x, acc.y, false);
    uint32_t ph1 = pack2_bf16(acc.z, acc.w, false);
    uint32_t pl0 = pack2_bf16(acc.x, acc.y, true);
    uint32_t pl1 = pack2_bf16(acc.z, acc.w, true);
    __nv_bfloat16* row = g_A3 + (size_t)node * 512;
    *(uint2*)(row + lane * 4)       = make_uint2(ph0, ph1);
    *(uint2*)(row + 256 + lane * 4) = make_uint2(pl0, pl1);
}

// ---------------- mma helpers ----------------
__device__ __forceinline__ uint32_t smem_to_u32(const void* p) {
    uint32_t a;
    asm("{ .reg .u64 t; cvta.to.shared.u64 t, %1; cvt.u32.u64 %0, t; }"
        : "=r"(a) : "l"(p));
    return a;
}
__device__ __forceinline__ void ldsm4(uint32_t* r, uint32_t addr) {
    asm volatile("ldmatrix.sync.aligned.m8n8.x4.shared.b16 {%0,%1,%2,%3}, [%4];"
                 : "=r"(r[0]), "=r"(r[1]), "=r"(r[2]), "=r"(r[3]) : "r"(addr));
}
__device__ __forceinline__ void mma16816(float* d, const uint32_t* a,
                                         uint32_t b0, uint32_t b1) {
    asm volatile("mma.sync.aligned.m16n8k16.row.col.f32.bf16.bf16.f32 "
                 "{%0,%1,%2,%3}, {%4,%5,%6,%7}, {%8,%9}, {%0,%1,%2,%3};"
                 : "+f"(d[0]), "+f"(d[1]), "+f"(d[2]), "+f"(d[3])
                 : "r"(a[0]), "r"(a[1]), "r"(a[2]), "r"(a[3]), "r"(b0), "r"(b1));
}

// ---------------- double-buffered HMMA GEMM (layer 1) + fused s,p epilogue ----------------
#define TST 40
__global__ __launch_bounds__(256, 2)
void mma_dense_kernel(const __nv_bfloat16* __restrict__ B3,  // [128,768]
                      const float* __restrict__ bias) {
    __shared__ __align__(16) __nv_bfloat16 sA[2][128 * TST];
    __shared__ __align__(16) __nv_bfloat16 sB[2][128 * TST];
    __shared__ float sS[128], sP[128];

    const int tid = threadIdx.x;
    const int lane = tid & 31;
    const int wid = tid >> 5;
    const int wm = wid & 3;
    const int wn = wid >> 2;
    const int row0 = blockIdx.x * 128;

    const int lrow = tid >> 1;
    const int lu = (tid & 1) * 2;
    const int gr = row0 + lrow;
    const __nv_bfloat16* arow = g_A3 + (size_t)gr * 512;
    const __nv_bfloat16* brow = B3 + (size_t)lrow * 768;

    const uint32_t offA = (uint32_t)((wm * 32 + (lane & 15)) * TST + (lane >> 4) * 8) * 2;
    const int gB = lane >> 3, lr = lane & 7;
    const uint32_t offB = (uint32_t)((wn * 64 + (gB >> 1) * 8 + lr) * TST + (gB & 1) * 8) * 2;
    uint32_t aS[2], bS[2];
    aS[0] = smem_to_u32(&sA[0][0]) + offA;
    aS[1] = smem_to_u32(&sA[1][0]) + offA;
    bS[0] = smem_to_u32(&sB[0][0]) + offB;
    bS[1] = smem_to_u32(&sB[1][0]) + offB;

    if (tid < 128) { sS[tid] = 0.f; sP[tid] = 0.f; }

    float d[2][8][4];
#pragma unroll
    for (int i = 0; i < 2; i++)
#pragma unroll
        for (int j = 0; j < 8; j++)
#pragma unroll
            for (int q = 0; q < 4; q++) d[i][j][q] = 0.f;

    uint4 rA0, rA1, rB0, rB1;
#define LDG_CHUNK(c) do { \
        int kb = (c) * 32; \
        int acol = (kb < 512) ? kb : (kb - 512); \
        if (gr < N_NODES) { \
            rA0 = *(const uint4*)(arow + acol + lu * 8); \
            rA1 = *(const uint4*)(arow + acol + lu * 8 + 8); \
        } else { \
            rA0 = make_uint4(0u, 0u, 0u, 0u); rA1 = rA0; \
        } \
        rB0 = *(const uint4*)(brow + kb + lu * 8); \
        rB1 = *(const uint4*)(brow + kb + lu * 8 + 8); \
    } while (0)
#define STS_CHUNK(st) do { \
        *(uint4*)&sA[st][lrow * TST + lu * 8]       = rA0; \
        *(uint4*)&sA[st][lrow * TST + (lu + 1) * 8] = rA1; \
        *(uint4*)&sB[st][lrow * TST + lu * 8]       = rB0; \
        *(uint4*)&sB[st][lrow * TST + (lu + 1) * 8] = rB1; \
    } while (0)

    LDG_CHUNK(0);
    STS_CHUNK(0);
    __syncthreads();

#pragma unroll 1
    for (int c = 0; c < 24; c++) {
        const int st = c & 1;
        if (c < 23) LDG_CHUNK(c + 1);
#pragma unroll
        for (int ks = 0; ks < 2; ks++) {
            uint32_t a[2][4], b[4][4];
#pragma unroll
            for (int mt = 0; mt < 2; mt++)
                ldsm4(a[mt], aS[st] + (uint32_t)(mt * 16 * TST + ks * 16) * 2);
#pragma unroll
            for (int p = 0; p < 4; p++)
                ldsm4(b[p], bS[st] + (uint32_t)(p * 16 * TST + ks * 16) * 2);
#pragma unroll
            for (int mt = 0; mt < 2; mt++)
#pragma unroll
                for (int p = 0; p < 4; p++) {
                    mma16816(d[mt][2 * p],     a[mt], b[p][0], b[p][1]);
                    mma16816(d[mt][2 * p + 1], a[mt], b[p][2], b[p][3]);
                }
        }
        if (c < 23) STS_CHUNK(st ^ 1);
        __syncthreads();
    }

    // ---- fused epilogue: relu(+bias), dot with u/v, block-reduce to s,p ----
    const int qrow = lane >> 2;
    const int qcol = (lane & 3) * 2;
#pragma unroll
    for (int mt = 0; mt < 2; mt++) {
        float sa = 0.f, pa = 0.f;
        float sb = 0.f, pb = 0.f;
#pragma unroll
        for (int nt = 0; nt < 8; nt++) {
            int cc = wn * 64 + nt * 8 + qcol;
            float b0 = bias[cc], b1 = bias[cc + 1];
            float2 u2 = *(const float2*)&g_u[cc];
            float2 v2 = *(const float2*)&g_v[cc];
            float v0 = fmaxf(d[mt][nt][0] + b0, 0.f);
            float v1 = fmaxf(d[mt][nt][1] + b1, 0.f);
            float v2_ = fmaxf(d[mt][nt][2] + b0, 0.f);
            float v3 = fmaxf(d[mt][nt][3] + b1, 0.f);
            sa = fmaf(v0, u2.x, sa); sa = fmaf(v1, u2.y, sa);
            pa = fmaf(v0, v2.x, pa); pa = fmaf(v1, v2.y, pa);
            sb = fmaf(v2_, u2.x, sb); sb = fmaf(v3, u2.y, sb);
            pb = fmaf(v2_, v2.x, pb); pb = fmaf(v3, v2.y, pb);
        }
#pragma unroll
        for (int off = 1; off <= 2; off <<= 1) {
            sa += __shfl_xor_sync(0xffffffffu, sa, off);
            pa += __shfl_xor_sync(0xffffffffu, pa, off);
            sb += __shfl_xor_sync(0xffffffffu, sb, off);
            pb += __shfl_xor_sync(0xffffffffu, pb, off);
        }
        if ((lane & 3) == 0) {
            int rl = wm * 32 + mt * 16 + qrow;
            atomicAdd(&sS[rl], sa);
            atomicAdd(&sP[rl], pa);
            atomicAdd(&sS[rl + 8], sb);
            atomicAdd(&sP[rl + 8], pb);
        }
    }
    __syncthreads();
    if (tid < 128) {
        int m = row0 + tid;
        if (m < N_NODES) {
            g_s[m] = sS[tid];
            g_p[m] = sP[tid];
        }
    }
}

// ---------------- layer-2 folded vectors: u = Wr2.w, v = Wt2.w, c0 = b2.w ----------------
__global__ void uv_kernel(const float* __restrict__ Wr2,
                          const float* __restrict__ Wt2,
                          const float* __restrict__ Wl,
                          const float* __restrict__ b2) {
    int k = threadIdx.x;   // 128
    float u = 0.f, v = 0.f;
#pragma unroll 4
    for (int n = 0; n < HID; n++) {
        float w = Wl[n];
        u = fmaf(Wr2[k * HID + n], w, u);
        v = fmaf(Wt2[k * HID + n], w, v);
    }
    g_u[k] = u;
    g_v[k] = v;
    __shared__ float red[HID];
    red[k] = b2[k] * Wl[k];
    __syncthreads();
    for (int off = 64; off; off >>= 1) {
        if (k < off) red[k] += red[k + off];
        __syncthreads();
    }
    if (k == 0) g_c0 = red[0];
}

// ---------------- final: per-graph reduce + sigmoid; re-zeroes g_deg ----------------
__global__ void final_kernel(const float* __restrict__ bl, float* __restrict__ out) {
    int g = blockIdx.x;
    int t = threadIdx.x;   // 256
    // re-zero deg for the next launch (g_deg is zero at process start; this
    // keeps every call's pre-state identical)
    int z = g * 256 + t;
    if (z < N_NODES) g_deg[z] = 0;

    int nbeg = g_start[g], nend = g_start[g + 1];
    int ebeg = g_rowptr[nbeg], eend = g_rowptr[nend];
    float local = 0.f;
    for (int p = ebeg + t; p < eend; p += 256) local += g_s[g_csr_src[p]];
    for (int n = nbeg + t; n < nend; n += 256) local += g_p[n];
    __shared__ float red[8];
#pragma unroll
    for (int off = 16; off; off >>= 1) local += __shfl_xor_sync(0xffffffffu, local, off);
    if ((t & 31) == 0) red[t >> 5] = local;
    __syncthreads();
    if (t == 0) {
        float tot = 0.f;
#pragma unroll
        for (int i = 0; i < 8; i++) tot += red[i];
        float cnt = (float)(nend - nbeg);
        float zz = (tot + cnt * g_c0) / fmaxf(cnt, 1.f) + bl[0];
        out[g] = 1.f / (1.f + expf(-zz));
    }
}

// ---------------- launch ----------------
extern "C" void kernel_launch(void* const* d_in, const int* in_sizes, int n_in,
                              void* d_out, int out_size) {
    const float* x      = (const float*)d_in[0];
    const int*   ei     = (const int*)d_in[1];
    const int*   batch  = (const int*)d_in[2];
    const float* W_rel0 = (const float*)d_in[3];
    const float* b_rel0 = (const float*)d_in[4];
    const float* W_root0= (const float*)d_in[5];
    const float* W_rel1 = (const float*)d_in[6];
    const float* b_rel1 = (const float*)d_in[7];
    const float* W_root1= (const float*)d_in[8];
    const float* W_rel2 = (const float*)d_in[9];
    const float* b_rel2 = (const float*)d_in[10];
    const float* W_root2= (const float*)d_in[11];
    const float* W_lin  = (const float*)d_in[12];
    const float* b_lin  = (const float*)d_in[13];
    float* out = (float*)d_out;

    __nv_bfloat16* B3_p;
    cudaGetSymbolAddress((void**)&B3_p, g_B3);

    // ---- CSR build (by dst) + precomputes ----
    hist_b3_kernel<<<(N_EDGES / 4 + 255) / 256, 256>>>(ei, W_rel1, W_root1);
    scan_starts_kernel<<<1, 1024>>>(batch);
    fill_kernel<<<(N_EDGES / 4 + 255) / 256, 256>>>(ei);
    uv_kernel<<<1, 128>>>(W_rel2, W_root2, W_lin, b_rel2);

    // ---- layer 0 ----
    gather5_kernel<<<(N_NODES + 255) / 256, 256>>>(x);
    layer0_dense_kernel<<<(N_NODES + 3) / 4, 512>>>(x, W_rel0, b_rel0, W_root0);

    // ---- layer 1 (GEMM with fused s,p epilogue) ----
    gather128_kernel<<<(N_NODES * 32 + 255) / 256, 256>>>();
    mma_dense_kernel<<<(N_NODES + 127) / 128, 256>>>(B3_p, b_rel1);

    // ---- pool + head ----
    final_kernel<<<NUM_GRAPHS, 256>>>(b_lin, out);
}

// round 15
// speedup vs baseline: 1.0899x; 1.0899x over previous
#include <cuda_runtime.h>
#include <cuda_bf16.h>
#include <math.h>
#include <stdint.h>

#define N_NODES 50000
#define N_EDGES 640000
#define IN_DIM  5
#define HID     128
#define NUM_GRAPHS 512

// ---------------- scratch (no allocations allowed) ----------------
__device__ float g_agg5[(size_t)N_NODES * IN_DIM];
__device__ int   g_deg[N_NODES];          // zero at load; re-zeroed by final_kernel
__device__ int   g_rowptr[N_NODES + 1];
__device__ int   g_cursor[N_NODES];
__device__ int   g_csr_src[N_EDGES];
__device__ int   g_start[NUM_GRAPHS + 1];
__device__ float g_s[N_NODES];            // h2_j . u
__device__ float g_p[N_NODES];            // h2_j . v
__device__ float g_u[HID], g_v[HID], g_c0;
// A3: per node 512 bf16 = [agg_hi(128) | h_hi(128) | agg_lo(128) | h_lo(128)]
__device__ __align__(16) __nv_bfloat16 g_A3[(size_t)N_NODES * 512];
// B3: layer-1 weights [N=128 rows][K3=768] bf16, K-contiguous ([W_hi ; W_hi ; W_lo])
__device__ __align__(16) __nv_bfloat16 g_B3[128 * 768];

// ---------------- hist (4 edges/thread) + B3 precompute ----------------
__global__ void hist_b3_kernel(const int* __restrict__ ei,
                               const float* __restrict__ Wr1,
                               const float* __restrict__ Wt1) {
    int idx = blockIdx.x * blockDim.x + threadIdx.x;
    int e4 = idx * 4;
    if (e4 < N_EDGES) {
        int4 d4 = *(const int4*)(ei + N_EDGES + e4);
        atomicAdd(&g_deg[d4.x], 1);
        atomicAdd(&g_deg[d4.y], 1);
        atomicAdd(&g_deg[d4.z], 1);
        atomicAdd(&g_deg[d4.w], 1);
    }
    if (idx < 128 * 768) {
        int n = idx / 768;
        int k3 = idx % 768;
        int seg = k3 / 256, sk = k3 % 256;
        const float* W = (sk < 128) ? Wr1 : Wt1;
        float w = W[(sk & 127) * 128 + n];
        __nv_bfloat16 h = __float2bfloat16(w);
        __nv_bfloat16 v = (seg == 2) ? __float2bfloat16(w - __bfloat162float(h)) : h;
        g_B3[(size_t)n * 768 + k3] = v;
    }
}

// ---------------- scan + graph-segment starts (merged) ----------------
__global__ void scan_starts_kernel(const int* __restrict__ batch) {
    const int t = threadIdx.x;
    if (t <= NUM_GRAPHS) {
        int lo = 0, hi = N_NODES;
        while (lo < hi) {
            int mid = (lo + hi) >> 1;
            if (batch[mid] < t) lo = mid + 1;
            else hi = mid;
        }
        g_start[t] = lo;
    }
    __shared__ int ssum[1024];
    const int CH = (N_NODES + 1023) / 1024;
    int lo = t * CH, hi = min(lo + CH, N_NODES);
    int s = 0;
    for (int i = lo; i < hi; i++) s += g_deg[i];
    ssum[t] = s;
    __syncthreads();
    for (int off = 1; off < 1024; off <<= 1) {
        int v = (t >= off) ? ssum[t - off] : 0;
        __syncthreads();
        ssum[t] += v;
        __syncthreads();
    }
    int run = (t == 0) ? 0 : ssum[t - 1];
    for (int i = lo; i < hi; i++) {
        int d = g_deg[i];
        g_rowptr[i] = run;
        g_cursor[i] = run;
        run += d;
    }
    if (t == 1023) g_rowptr[N_NODES] = run;
}

// ---------------- fill (4 edges/thread) ----------------
__global__ void fill_kernel(const int* __restrict__ ei) {
    int idx = blockIdx.x * blockDim.x + threadIdx.x;
    int e4 = idx * 4;
    if (e4 >= N_EDGES) return;
    int4 s4 = *(const int4*)(ei + e4);
    int4 d4 = *(const int4*)(ei + N_EDGES + e4);
    int p0 = atomicAdd(&g_cursor[d4.x], 1);
    g_csr_src[p0] = s4.x;
    int p1 = atomicAdd(&g_cursor[d4.y], 1);
    g_csr_src[p1] = s4.y;
    int p2 = atomicAdd(&g_cursor[d4.z], 1);
    g_csr_src[p2] = s4.z;
    int p3 = atomicAdd(&g_cursor[d4.w], 1);
    g_csr_src[p3] = s4.w;
}

// ---------------- hi/lo bf16 pair packer ----------------
__device__ __forceinline__ uint32_t pack2_bf16(float fe, float fo, bool lo_mode) {
    uint32_t h;
    asm("cvt.rn.bf16x2.f32 %0, %1, %2;" : "=r"(h) : "f"(fo), "f"(fe));
    if (lo_mode) {
        float he = __uint_as_float(h << 16);
        float ho = __uint_as_float(h & 0xffff0000u);
        float le = fe - he;
        float lo_ = fo - ho;
        asm("cvt.rn.bf16x2.f32 %0, %1, %2;" : "=r"(h) : "f"(lo_), "f"(le));
    }
    return h;
}

// ---------------- layer 0: 5-dim gather ----------------
__global__ void gather5_kernel(const float* __restrict__ x) {
    int node = blockIdx.x * blockDim.x + threadIdx.x;
    if (node >= N_NODES) return;
    int beg = g_rowptr[node], end = g_rowptr[node + 1];
    float a0 = 0.f, a1 = 0.f, a2 = 0.f, a3 = 0.f, a4 = 0.f;
    for (int e = beg; e < end; e++) {
        const float* xs = x + (size_t)g_csr_src[e] * IN_DIM;
        a0 += xs[0]; a1 += xs[1]; a2 += xs[2]; a3 += xs[3]; a4 += xs[4];
    }
    float* o = g_agg5 + (size_t)node * IN_DIM;
    o[0] = a0; o[1] = a1; o[2] = a2; o[3] = a3; o[4] = a4;
}

// ---------------- layer 0: dense (K=5), writes A3 h_hi/h_lo ----------------
__global__ void layer0_dense_kernel(const float* __restrict__ x,
                                    const float* __restrict__ Wr,
                                    const float* __restrict__ br,
                                    const float* __restrict__ Wt) {
    int n = blockIdx.x * 4 + (threadIdx.x >> 7);
    int o = threadIdx.x & 127;
    if (n >= N_NODES) return;
    float acc = br[o];
#pragma unroll
    for (int i = 0; i < IN_DIM; i++) {
        acc = fmaf(g_agg5[(size_t)n * IN_DIM + i], Wr[i * HID + o], acc);
        acc = fmaf(x[(size_t)n * IN_DIM + i],     Wt[i * HID + o], acc);
    }
    float v = fmaxf(acc, 0.f);
    __nv_bfloat16 hb = __float2bfloat16(v);
    g_A3[(size_t)n * 512 + 128 + o] = hb;
    g_A3[(size_t)n * 512 + 384 + o] = __float2bfloat16(v - __bfloat162float(hb));
}

// ---------------- 128-dim gather over A3 h_hi/h_lo -> A3 agg_hi/agg_lo ----------------
__device__ __forceinline__ void acc2(float& fe, float& fo, uint32_t w) {
    fe += __uint_as_float(w << 16);
    fo += __uint_as_float(w & 0xffff0000u);
}

__global__ void gather128_kernel() {
    int node = (blockIdx.x * blockDim.x + threadIdx.x) >> 5;
    int lane = threadIdx.x & 31;
    if (node >= N_NODES) return;
    int beg = g_rowptr[node], end = g_rowptr[node + 1];
    float4 acc = make_float4(0.f, 0.f, 0.f, 0.f);
    const __nv_bfloat16* A3 = g_A3;
    int e = beg;
    for (; e + 3 < end; e += 4) {
        int s0 = g_csr_src[e + 0];
        int s1 = g_csr_src[e + 1];
        int s2 = g_csr_src[e + 2];
        int s3 = g_csr_src[e + 3];
        uint2 h0 = *(const uint2*)(A3 + (size_t)s0 * 512 + 128 + lane * 4);
        uint2 l0 = *(const uint2*)(A3 + (size_t)s0 * 512 + 384 + lane * 4);
        uint2 h1 = *(const uint2*)(A3 + (size_t)s1 * 512 + 128 + lane * 4);
        uint2 l1 = *(const uint2*)(A3 + (size_t)s1 * 512 + 384 + lane * 4);
        uint2 h2 = *(const uint2*)(A3 + (size_t)s2 * 512 + 128 + lane * 4);
        uint2 l2 = *(const uint2*)(A3 + (size_t)s2 * 512 + 384 + lane * 4);
        uint2 h3 = *(const uint2*)(A3 + (size_t)s3 * 512 + 128 + lane * 4);
        uint2 l3 = *(const uint2*)(A3 + (size_t)s3 * 512 + 384 + lane * 4);
        acc2(acc.x, acc.y, h0.x); acc2(acc.z, acc.w, h0.y);
        acc2(acc.x, acc.y, l0.x); acc2(acc.z, acc.w, l0.y);
        acc2(acc.x, acc.y, h1.x); acc2(acc.z, acc.w, h1.y);
        acc2(acc.x, acc.y, l1.x); acc2(acc.z, acc.w, l1.y);
        acc2(acc.x, acc.y, h2.x); acc2(acc.z, acc.w, h2.y);
        acc2(acc.x, acc.y, l2.x); acc2(acc.z, acc.w, l2.y);
        acc2(acc.x, acc.y, h3.x); acc2(acc.z, acc.w, h3.y);
        acc2(acc.x, acc.y, l3.x); acc2(acc.z, acc.w, l3.y);
    }
    for (; e < end; e++) {
        int s0 = g_csr_src[e];
        uint2 h0 = *(const uint2*)(A3 + (size_t)s0 * 512 + 128 + lane * 4);
        uint2 l0 = *(const uint2*)(A3 + (size_t)s0 * 512 + 384 + lane * 4);
        acc2(acc.x, acc.y, h0.x); acc2(acc.z, acc.w, h0.y);
        acc2(acc.x, acc.y, l0.x); acc2(acc.z, acc.w, l0.y);
    }
    uint32_t ph0 = pack2_bf16(acc.x, acc.y, false);
    uint32_t ph1 = pack2_bf16(acc.z, acc.w, false);
    uint32_t pl0 = pack2_bf16(acc.x, acc.y, true);
    uint32_t pl1 = pack2_bf16(acc.z, acc.w, true);
    __nv_bfloat16* row = g_A3 + (size_t)node * 512;
    *(uint2*)(row + lane * 4)       = make_uint2(ph0, ph1);
    *(uint2*)(row + 256 + lane * 4) = make_uint2(pl0, pl1);
}

// ---------------- mma helpers ----------------
__device__ __forceinline__ uint32_t smem_to_u32(const void* p) {
    uint32_t a;
    asm("{ .reg .u64 t; cvta.to.shared.u64 t, %1; cvt.u32.u64 %0, t; }"
        : "=r"(a) : "l"(p));
    return a;
}
__device__ __forceinline__ void ldsm4(uint32_t* r, uint32_t addr) {
    asm volatile("ldmatrix.sync.aligned.m8n8.x4.shared.b16 {%0,%1,%2,%3}, [%4];"
                 : "=r"(r[0]), "=r"(r[1]), "=r"(r[2]), "=r"(r[3]) : "r"(addr));
}
__device__ __forceinline__ void mma16816(float* d, const uint32_t* a,
                                         uint32_t b0, uint32_t b1) {
    asm volatile("mma.sync.aligned.m16n8k16.row.col.f32.bf16.bf16.f32 "
                 "{%0,%1,%2,%3}, {%4,%5,%6,%7}, {%8,%9}, {%0,%1,%2,%3};"
                 : "+f"(d[0]), "+f"(d[1]), "+f"(d[2]), "+f"(d[3])
                 : "r"(a[0]), "r"(a[1]), "r"(a[2]), "r"(a[3]), "r"(b0), "r"(b1));
}

// ---------------- double-buffered HMMA GEMM (layer 1) + fused s,p epilogue ----------------
#define TST 40
__global__ __launch_bounds__(256, 2)
void mma_dense_kernel(const __nv_bfloat16* __restrict__ B3,  // [128,768]
                      const float* __restrict__ bias) {
    __shared__ __align__(16) __nv_bfloat16 sA[2][128 * TST];
    __shared__ __align__(16) __nv_bfloat16 sB[2][128 * TST];
    __shared__ float sS[128], sP[128];

    const int tid = threadIdx.x;
    const int lane = tid & 31;
    const int wid = tid >> 5;
    const int wm = wid & 3;
    const int wn = wid >> 2;
    const int row0 = blockIdx.x * 128;

    const int lrow = tid >> 1;
    const int lu = (tid & 1) * 2;
    const int gr = row0 + lrow;
    const __nv_bfloat16* arow = g_A3 + (size_t)gr * 512;
    const __nv_bfloat16* brow = B3 + (size_t)lrow * 768;

    const uint32_t offA = (uint32_t)((wm * 32 + (lane & 15)) * TST + (lane >> 4) * 8) * 2;
    const int gB = lane >> 3, lr = lane & 7;
    const uint32_t offB = (uint32_t)((wn * 64 + (gB >> 1) * 8 + lr) * TST + (gB & 1) * 8) * 2;
    uint32_t aS[2], bS[2];
    aS[0] = smem_to_u32(&sA[0][0]) + offA;
    aS[1] = smem_to_u32(&sA[1][0]) + offA;
    bS[0] = smem_to_u32(&sB[0][0]) + offB;
    bS[1] = smem_to_u32(&sB[1][0]) + offB;

    if (tid < 128) { sS[tid] = 0.f; sP[tid] = 0.f; }

    float d[2][8][4];
#pragma unroll
    for (int i = 0; i < 2; i++)
#pragma unroll
        for (int j = 0; j < 8; j++)
#pragma unroll
            for (int q = 0; q < 4; q++) d[i][j][q] = 0.f;

    uint4 rA0, rA1, rB0, rB1;
#define LDG_CHUNK(c) do { \
        int kb = (c) * 32; \
        int acol = (kb < 512) ? kb : (kb - 512); \
        if (gr < N_NODES) { \
            rA0 = *(const uint4*)(arow + acol + lu * 8); \
            rA1 = *(const uint4*)(arow + acol + lu * 8 + 8); \
        } else { \
            rA0 = make_uint4(0u, 0u, 0u, 0u); rA1 = rA0; \
        } \
        rB0 = *(const uint4*)(brow + kb + lu * 8); \
        rB1 = *(const uint4*)(brow + kb + lu * 8 + 8); \
    } while (0)
#define STS_CHUNK(st) do { \
        *(uint4*)&sA[st][lrow * TST + lu * 8]       = rA0; \
        *(uint4*)&sA[st][lrow * TST + (lu + 1) * 8] = rA1; \
        *(uint4*)&sB[st][lrow * TST + lu * 8]       = rB0; \
        *(uint4*)&sB[st][lrow * TST + (lu + 1) * 8] = rB1; \
    } while (0)

    LDG_CHUNK(0);
    STS_CHUNK(0);
    __syncthreads();

#pragma unroll 1
    for (int c = 0; c < 24; c++) {
        const int st = c & 1;
        if (c < 23) LDG_CHUNK(c + 1);
#pragma unroll
        for (int ks = 0; ks < 2; ks++) {
            uint32_t a[2][4], b[4][4];
#pragma unroll
            for (int mt = 0; mt < 2; mt++)
                ldsm4(a[mt], aS[st] + (uint32_t)(mt * 16 * TST + ks * 16) * 2);
#pragma unroll
            for (int p = 0; p < 4; p++)
                ldsm4(b[p], bS[st] + (uint32_t)(p * 16 * TST + ks * 16) * 2);
#pragma unroll
            for (int mt = 0; mt < 2; mt++)
#pragma unroll
                for (int p = 0; p < 4; p++) {
                    mma16816(d[mt][2 * p],     a[mt], b[p][0], b[p][1]);
                    mma16816(d[mt][2 * p + 1], a[mt], b[p][2], b[p][3]);
                }
        }
        if (c < 23) STS_CHUNK(st ^ 1);
        __syncthreads();
    }

    // ---- fused epilogue: relu(+bias), dot with u/v, block-reduce to s,p ----
    const int qrow = lane >> 2;
    const int qcol = (lane & 3) * 2;
#pragma unroll
    for (int mt = 0; mt < 2; mt++) {
        float sa = 0.f, pa = 0.f;
        float sb = 0.f, pb = 0.f;
#pragma unroll
        for (int nt = 0; nt < 8; nt++) {
            int cc = wn * 64 + nt * 8 + qcol;
            float b0 = bias[cc], b1 = bias[cc + 1];
            float2 u2 = *(const float2*)&g_u[cc];
            float2 v2 = *(const float2*)&g_v[cc];
            float v0 = fmaxf(d[mt][nt][0] + b0, 0.f);
            float v1 = fmaxf(d[mt][nt][1] + b1, 0.f);
            float v2_ = fmaxf(d[mt][nt][2] + b0, 0.f);
            float v3 = fmaxf(d[mt][nt][3] + b1, 0.f);
            sa = fmaf(v0, u2.x, sa); sa = fmaf(v1, u2.y, sa);
            pa = fmaf(v0, v2.x, pa); pa = fmaf(v1, v2.y, pa);
            sb = fmaf(v2_, u2.x, sb); sb = fmaf(v3, u2.y, sb);
            pb = fmaf(v2_, v2.x, pb); pb = fmaf(v3, v2.y, pb);
        }
#pragma unroll
        for (int off = 1; off <= 2; off <<= 1) {
            sa += __shfl_xor_sync(0xffffffffu, sa, off);
            pa += __shfl_xor_sync(0xffffffffu, pa, off);
            sb += __shfl_xor_sync(0xffffffffu, sb, off);
            pb += __shfl_xor_sync(0xffffffffu, pb, off);
        }
        if ((lane & 3) == 0) {
            int rl = wm * 32 + mt * 16 + qrow;
            atomicAdd(&sS[rl], sa);
            atomicAdd(&sP[rl], pa);
            atomicAdd(&sS[rl + 8], sb);
            atomicAdd(&sP[rl + 8], pb);
        }
    }
    __syncthreads();
    if (tid < 128) {
        int m = row0 + tid;
        if (m < N_NODES) {
            g_s[m] = sS[tid];
            g_p[m] = sP[tid];
        }
    }
}

// ---------------- layer-2 folded vectors (PARALLEL): u = Wr2.w, v = Wt2.w, c0 = b2.w ----------------
// grid = 128 blocks, 128 threads. Block k reduces over n for u[k], v[k].
// Block 0 additionally computes c0 = sum_n b2[n]*Wl[n].
__global__ void uv_kernel(const float* __restrict__ Wr2,
                          const float* __restrict__ Wt2,
                          const float* __restrict__ Wl,
                          const float* __restrict__ b2) {
    const int k = blockIdx.x;     // output index
    const int n = threadIdx.x;    // reduction index
    float w = Wl[n];
    float pu = Wr2[k * HID + n] * w;
    float pv = Wt2[k * HID + n] * w;
    float pc = (k == 0) ? b2[n] * w : 0.f;
    __shared__ float ru[4], rv[4], rc[4];
#pragma unroll
    for (int off = 16; off; off >>= 1) {
        pu += __shfl_xor_sync(0xffffffffu, pu, off);
        pv += __shfl_xor_sync(0xffffffffu, pv, off);
        pc += __shfl_xor_sync(0xffffffffu, pc, off);
    }
    if ((n & 31) == 0) {
        ru[n >> 5] = pu;
        rv[n >> 5] = pv;
        rc[n >> 5] = pc;
    }
    __syncthreads();
    if (n == 0) {
        g_u[k] = ru[0] + ru[1] + ru[2] + ru[3];
        g_v[k] = rv[0] + rv[1] + rv[2] + rv[3];
        if (k == 0) g_c0 = rc[0] + rc[1] + rc[2] + rc[3];
    }
}

// ---------------- final: per-graph reduce + sigmoid; re-zeroes g_deg ----------------
__global__ void final_kernel(const float* __restrict__ bl, float* __restrict__ out) {
    int g = blockIdx.x;
    int t = threadIdx.x;   // 256
    // re-zero deg for the next call (zero at process start; keeps pre-state identical)
    int z = g * 256 + t;
    if (z < N_NODES) g_deg[z] = 0;

    int nbeg = g_start[g], nend = g_start[g + 1];
    int ebeg = g_rowptr[nbeg], eend = g_rowptr[nend];
    float local = 0.f;
    for (int p = ebeg + t; p < eend; p += 256) local += g_s[g_csr_src[p]];
    for (int n = nbeg + t; n < nend; n += 256) local += g_p[n];
    __shared__ float red[8];
#pragma unroll
    for (int off = 16; off; off >>= 1) local += __shfl_xor_sync(0xffffffffu, local, off);
    if ((t & 31) == 0) red[t >> 5] = local;
    __syncthreads();
    if (t == 0) {
        float tot = 0.f;
#pragma unroll
        for (int i = 0; i < 8; i++) tot += red[i];
        float cnt = (float)(nend - nbeg);
        float zz = (tot + cnt * g_c0) / fmaxf(cnt, 1.f) + bl[0];
        out[g] = 1.f / (1.f + expf(-zz));
    }
}

// ---------------- launch ----------------
extern "C" void kernel_launch(void* const* d_in, const int* in_sizes, int n_in,
                              void* d_out, int out_size) {
    const float* x      = (const float*)d_in[0];
    const int*   ei     = (const int*)d_in[1];
    const int*   batch  = (const int*)d_in[2];
    const float* W_rel0 = (const float*)d_in[3];
    const float* b_rel0 = (const float*)d_in[4];
    const float* W_root0= (const float*)d_in[5];
    const float* W_rel1 = (const float*)d_in[6];
    const float* b_rel1 = (const float*)d_in[7];
    const float* W_root1= (const float*)d_in[8];
    const float* W_rel2 = (const float*)d_in[9];
    const float* b_rel2 = (const float*)d_in[10];
    const float* W_root2= (const float*)d_in[11];
    const float* W_lin  = (const float*)d_in[12];
    const float* b_lin  = (const float*)d_in[13];
    float* out = (float*)d_out;

    __nv_bfloat16* B3_p;
    cudaGetSymbolAddress((void**)&B3_p, g_B3);

    // ---- CSR build (by dst) + precomputes ----
    hist_b3_kernel<<<(N_EDGES / 4 + 255) / 256, 256>>>(ei, W_rel1, W_root1);
    scan_starts_kernel<<<1, 1024>>>(batch);
    fill_kernel<<<(N_EDGES / 4 + 255) / 256, 256>>>(ei);
    uv_kernel<<<HID, 128>>>(W_rel2, W_root2, W_lin, b_rel2);

    // ---- layer 0 ----
    gather5_kernel<<<(N_NODES + 255) / 256, 256>>>(x);
    layer0_dense_kernel<<<(N_NODES + 3) / 4, 512>>>(x, W_rel0, b_rel0, W_root0);

    // ---- layer 1 (GEMM with fused s,p epilogue) ----
    gather128_kernel<<<(N_NODES * 32 + 255) / 256, 256>>>();
    mma_dense_kernel<<<(N_NODES + 127) / 128, 256>>>(B3_p, b_rel1);

    // ---- pool + head ----
    final_kernel<<<NUM_GRAPHS, 256>>>(b_lin, out);
}